// round 10
// baseline (speedup 1.0000x reference)
#include <cuda_runtime.h>

// Comparator4Bit: A,B are [N,4] float32 with exact {0,1} entries (MSB first).
// Outputs: a_gt_b [N], a_eq_b [N], concatenated into d_out (2N floats).
//
// R9: software-pipelined 16 rows/thread (two batches of 8). Batch 1's loads
// are issued before batch 0's stores, so store issue overlaps load latency.
// 512-thread blocks, warp-stride coalesced 128-bit __ldcs loads, default
// coalesced scalar stores (streaming stores proved harmful in R5/R7),
// launch_bounds(512,4) reg cap (proved neutral-safe in R8).

#define BATCH_ROWS     8
#define BLOCK_THREADS  512
#define TILE_ROWS      (BLOCK_THREADS * BATCH_ROWS * 2)   // 8192

__global__ __launch_bounds__(BLOCK_THREADS, 4) void cmp4_kernel(
    const uint4* __restrict__ A,    // one uint4 per row
    const uint4* __restrict__ B,
    float* __restrict__ gt_out,     // N floats
    float* __restrict__ eq_out)     // N floats
{
    const int base0 = blockIdx.x * TILE_ROWS + threadIdx.x;          // batch 0
    const int base1 = base0 + BLOCK_THREADS * BATCH_ROWS;            // batch 1

    // Batch 0 loads.
    uint4 a0[BATCH_ROWS], b0[BATCH_ROWS];
    #pragma unroll
    for (int k = 0; k < BATCH_ROWS; k++) {
        int row = base0 + k * BLOCK_THREADS;
        a0[k] = __ldcs(&A[row]);
        b0[k] = __ldcs(&B[row]);
    }

    // Batch 1 loads issued before batch 0 stores -> stores overlap load latency.
    uint4 a1[BATCH_ROWS], b1[BATCH_ROWS];
    #pragma unroll
    for (int k = 0; k < BATCH_ROWS; k++) {
        int row = base1 + k * BLOCK_THREADS;
        a1[k] = __ldcs(&A[row]);
        b1[k] = __ldcs(&B[row]);
    }

    // Batch 0 compute + store.
    #pragma unroll
    for (int k = 0; k < BATCH_ROWS; k++) {
        int row = base0 + k * BLOCK_THREADS;
        int av = ((a0[k].x != 0u) << 3) | ((a0[k].y != 0u) << 2) |
                 ((a0[k].z != 0u) << 1) |  (a0[k].w != 0u);
        int bv = ((b0[k].x != 0u) << 3) | ((b0[k].y != 0u) << 2) |
                 ((b0[k].z != 0u) << 1) |  (b0[k].w != 0u);
        gt_out[row] = (av > bv)  ? 1.0f : 0.0f;
        eq_out[row] = (av == bv) ? 1.0f : 0.0f;
    }

    // Batch 1 compute + store.
    #pragma unroll
    for (int k = 0; k < BATCH_ROWS; k++) {
        int row = base1 + k * BLOCK_THREADS;
        int av = ((a1[k].x != 0u) << 3) | ((a1[k].y != 0u) << 2) |
                 ((a1[k].z != 0u) << 1) |  (a1[k].w != 0u);
        int bv = ((b1[k].x != 0u) << 3) | ((b1[k].y != 0u) << 2) |
                 ((b1[k].z != 0u) << 1) |  (b1[k].w != 0u);
        gt_out[row] = (av > bv)  ? 1.0f : 0.0f;
        eq_out[row] = (av == bv) ? 1.0f : 0.0f;
    }
}

extern "C" void kernel_launch(void* const* d_in, const int* in_sizes, int n_in,
                              void* d_out, int out_size)
{
    const uint4* A = (const uint4*)d_in[0];
    const uint4* B = (const uint4*)d_in[1];
    int n_rows = in_sizes[0] / 4;          // N = 2^23

    float* out = (float*)d_out;
    float* gt_out = out;                   // first N floats
    float* eq_out = out + n_rows;          // next N floats

    int blocks = n_rows / TILE_ROWS;       // 1024 (N is a power of two)
    cmp4_kernel<<<blocks, BLOCK_THREADS>>>(A, B, gt_out, eq_out);
}

// round 11
// speedup vs baseline: 1.3852x; 1.3852x over previous
#include <cuda_runtime.h>

// Comparator4Bit: A,B are [N,4] float32 with exact {0,1} entries (MSB first).
// Outputs: a_gt_b [N], a_eq_b [N], concatenated into d_out (2N floats).
//
// FINAL (== R6, best measured kernel: 44.48us, DRAM 77.4% / 6.32TB/s):
//  - 512-thread blocks, one 4096-row tile per block.
//  - Warp-stride layout: consecutive lanes load consecutive 16B rows ->
//    every LDG.128 touches exactly 4 cache lines (perfect coalescing).
//  - 16 independent front-batched __ldcs (evict-first; zero-reuse inputs).
//  - Default-policy coalesced scalar stores (__stcs measured harmful R5/R7).
//  - No reg cap (R9 showed capping + batching causes spills; R8 showed the
//    occupancy gain from capping is worthless — kernel is HBM-ceiling-bound).
//  - Bit trick: entries are exactly 0.0f/1.0f, so pack 4 bits per row and
//    compare ints; bit-identical to the reference boolean arithmetic.

#define ROWS_PER_THREAD 8
#define BLOCK_THREADS   512
#define TILE_ROWS       (BLOCK_THREADS * ROWS_PER_THREAD)   // 4096

__global__ __launch_bounds__(BLOCK_THREADS) void cmp4_kernel(
    const uint4* __restrict__ A,    // one uint4 per row
    const uint4* __restrict__ B,
    float* __restrict__ gt_out,     // N floats
    float* __restrict__ eq_out)     // N floats
{
    const int tile = blockIdx.x * TILE_ROWS;

    // Front-batch 16 independent, perfectly coalesced 128-bit streaming loads.
    uint4 a[ROWS_PER_THREAD], b[ROWS_PER_THREAD];
    #pragma unroll
    for (int k = 0; k < ROWS_PER_THREAD; k++) {
        int row = tile + k * BLOCK_THREADS + threadIdx.x;
        a[k] = __ldcs(&A[row]);
        b[k] = __ldcs(&B[row]);
    }

    #pragma unroll
    for (int k = 0; k < ROWS_PER_THREAD; k++) {
        int row = tile + k * BLOCK_THREADS + threadIdx.x;
        // Values are exactly 0.0f or 1.0f: nonzero pattern == logical 1.
        int av = ((a[k].x != 0u) << 3) | ((a[k].y != 0u) << 2) |
                 ((a[k].z != 0u) << 1) |  (a[k].w != 0u);
        int bv = ((b[k].x != 0u) << 3) | ((b[k].y != 0u) << 2) |
                 ((b[k].z != 0u) << 1) |  (b[k].w != 0u);
        gt_out[row] = (av > bv)  ? 1.0f : 0.0f;
        eq_out[row] = (av == bv) ? 1.0f : 0.0f;
    }
}

extern "C" void kernel_launch(void* const* d_in, const int* in_sizes, int n_in,
                              void* d_out, int out_size)
{
    const uint4* A = (const uint4*)d_in[0];
    const uint4* B = (const uint4*)d_in[1];
    int n_rows = in_sizes[0] / 4;          // N = 2^23

    float* out = (float*)d_out;
    float* gt_out = out;                   // first N floats
    float* eq_out = out + n_rows;          // next N floats

    int blocks = n_rows / TILE_ROWS;       // 2048 (N is a power of two)
    cmp4_kernel<<<blocks, BLOCK_THREADS>>>(A, B, gt_out, eq_out);
}